// round 2
// baseline (speedup 1.0000x reference)
#include <cuda_runtime.h>
#include <math.h>

// Problem constants
#define S_    1024
#define E_    1024
#define H_    16
#define HD_   64
#define B_    4
#define BH_   (B_ * H_)          // 64
#define RELN_ (2 * S_ - 1)       // 2047

// -------------------- scratch (device globals; no allocation) --------------------
__device__ float g_Q[(size_t)BH_ * S_ * HD_];        // [bh][s][hd]  16 MB
__device__ float g_K[(size_t)BH_ * S_ * HD_];        // 16 MB
__device__ float g_V[(size_t)BH_ * S_ * HD_];        // 16 MB
__device__ float g_ctx[(size_t)B_ * S_ * E_];        // [b][s][e]    16 MB
__device__ float g_relkey[(size_t)RELN_ * HD_];      // 0.5 MB
__device__ float g_scores[(size_t)BH_ * S_ * S_];    // 256 MB

// ==================================================================================
// GEMM NT + bias:  C[M,N] = A[M,K] @ B[N,K]^T + bias[N]
// mode 0: C row-major [M,N]
// mode 1: write to attention layout [b*H+h][s][hd]  (m = b*S+s, n = h*HD+hd)
// Tiles: 128x128x16, 256 threads, 8x8 microtile.
// ==================================================================================
__global__ __launch_bounds__(256) void gemm_nt_bias(
    const float* __restrict__ A, const float* __restrict__ Bw,
    const float* __restrict__ bias, float* __restrict__ C,
    int M, int N, int K, int mode)
{
    __shared__ __align__(16) float As[16][132];
    __shared__ __align__(16) float Bs[16][132];
    const int tid  = threadIdx.x;
    const int row0 = blockIdx.y * 128;
    const int col0 = blockIdx.x * 128;
    const int tm   = tid >> 4;
    const int tn   = tid & 15;

    float acc[8][8];
    #pragma unroll
    for (int i = 0; i < 8; i++)
        #pragma unroll
        for (int j = 0; j < 8; j++) acc[i][j] = 0.f;

    for (int k0 = 0; k0 < K; k0 += 16) {
        #pragma unroll
        for (int i = 0; i < 2; i++) {
            int f  = tid + i * 256;          // 0..511
            int r  = f >> 2;                 // tile row 0..127
            int cg = (f & 3) * 4;            // col group start (0,4,8,12)
            float4 va = *reinterpret_cast<const float4*>(&A[(size_t)(row0 + r) * K + k0 + cg]);
            As[cg + 0][r] = va.x; As[cg + 1][r] = va.y;
            As[cg + 2][r] = va.z; As[cg + 3][r] = va.w;
            float4 vb = *reinterpret_cast<const float4*>(&Bw[(size_t)(col0 + r) * K + k0 + cg]);
            Bs[cg + 0][r] = vb.x; Bs[cg + 1][r] = vb.y;
            Bs[cg + 2][r] = vb.z; Bs[cg + 3][r] = vb.w;
        }
        __syncthreads();
        #pragma unroll
        for (int kk = 0; kk < 16; kk++) {
            float a[8], b[8];
            *reinterpret_cast<float4*>(&a[0]) = *reinterpret_cast<const float4*>(&As[kk][tm * 8]);
            *reinterpret_cast<float4*>(&a[4]) = *reinterpret_cast<const float4*>(&As[kk][tm * 8 + 4]);
            *reinterpret_cast<float4*>(&b[0]) = *reinterpret_cast<const float4*>(&Bs[kk][tn * 8]);
            *reinterpret_cast<float4*>(&b[4]) = *reinterpret_cast<const float4*>(&Bs[kk][tn * 8 + 4]);
            #pragma unroll
            for (int i = 0; i < 8; i++)
                #pragma unroll
                for (int j = 0; j < 8; j++)
                    acc[i][j] = fmaf(a[i], b[j], acc[i][j]);
        }
        __syncthreads();
    }

    #pragma unroll
    for (int i = 0; i < 8; i++) {
        int m = row0 + tm * 8 + i;
        #pragma unroll
        for (int jg = 0; jg < 8; jg += 4) {
            int n = col0 + tn * 8 + jg;
            float4 o;
            o.x = acc[i][jg + 0] + bias[n + 0];
            o.y = acc[i][jg + 1] + bias[n + 1];
            o.z = acc[i][jg + 2] + bias[n + 2];
            o.w = acc[i][jg + 3] + bias[n + 3];
            if (mode == 0) {
                *reinterpret_cast<float4*>(&C[(size_t)m * N + n]) = o;
            } else {
                int bb = m >> 10;        // S = 1024
                int ss = m & 1023;
                int hh = n >> 6;         // HD = 64
                int hd = n & 63;
                size_t idx = (((size_t)(bb * H_ + hh)) * S_ + ss) * HD_ + hd;
                *reinterpret_cast<float4*>(&C[idx]) = o;
            }
        }
    }
}

// ==================================================================================
// rel_key[p, d] = sum_j rel_table[p, j] * Wp[d, j]     (2047 x 64) @ (64 x 64)^T
// ==================================================================================
__global__ __launch_bounds__(64) void relkey_kernel(
    const float* __restrict__ rel_table, const float* __restrict__ Wp,
    float* __restrict__ RK)
{
    __shared__ float w[64][65];
    __shared__ float rt[64];
    const int p = blockIdx.x;
    const int t = threadIdx.x;
    #pragma unroll
    for (int i = 0; i < 64; i++) w[i][t] = Wp[i * 64 + t];
    rt[t] = rel_table[(size_t)p * 64 + t];
    __syncthreads();
    float s = 0.f;
    #pragma unroll
    for (int j = 0; j < 64; j++) s = fmaf(w[t][j], rt[j], s);
    RK[(size_t)p * 64 + t] = s;
}

// ==================================================================================
// Fused content + rel-shifted position scores:
//   scores[bh, q, k] = scale * ( Q[bh,q] . K[bh,k] + Q[bh,q] . rel_key[S-1-q+k] )
// Block: 64x64 (q,k) tile for one bh. 256 threads, 4x4 microtile.
// D split in halves of 32 to keep static smem < 48KB.
// ==================================================================================
__global__ __launch_bounds__(256) void scores_kernel(
    const float* __restrict__ Q, const float* __restrict__ Kg,
    const float* __restrict__ RK, float* __restrict__ Sc)
{
    __shared__ __align__(16) float Qs[32][68];     // [d][q]
    __shared__ __align__(16) float Ks[32][68];     // [d][k]
    __shared__ __align__(16) float RKs[32][132];   // [d][jj], jj in [0,126]

    const int bh = blockIdx.z;
    const int q0 = blockIdx.y * 64;
    const int k0 = blockIdx.x * 64;
    const int jbase = (S_ - 64) - q0 + k0;         // 960 - q0 + k0, always in [0, 1920]
    const int tid = threadIdx.x;
    const int tm  = tid >> 4;                      // q group
    const int tn  = tid & 15;                      // k group

    const float* Qb = Q  + ((size_t)bh * S_ + q0) * HD_;
    const float* Kb = Kg + ((size_t)bh * S_ + k0) * HD_;
    const float* Rb = RK + (size_t)jbase * HD_;

    float accC[4][4], accP[4][4];
    #pragma unroll
    for (int i = 0; i < 4; i++)
        #pragma unroll
        for (int j = 0; j < 4; j++) { accC[i][j] = 0.f; accP[i][j] = 0.f; }

    const int base = 63 - tm * 4 + tn * 4;         // in [3, 123]

    for (int dd = 0; dd < 64; dd += 32) {
        // Q tile: 64 rows x 32 d = 512 float4, 2 per thread
        #pragma unroll
        for (int i = 0; i < 2; i++) {
            int f  = tid + i * 256;
            int r  = f >> 3;
            int cg = (f & 7) * 4;
            float4 v = *reinterpret_cast<const float4*>(&Qb[(size_t)r * HD_ + dd + cg]);
            Qs[cg + 0][r] = v.x; Qs[cg + 1][r] = v.y; Qs[cg + 2][r] = v.z; Qs[cg + 3][r] = v.w;
            float4 w = *reinterpret_cast<const float4*>(&Kb[(size_t)r * HD_ + dd + cg]);
            Ks[cg + 0][r] = w.x; Ks[cg + 1][r] = w.y; Ks[cg + 2][r] = w.z; Ks[cg + 3][r] = w.w;
        }
        // rel_key window: 127 rows x 32 d = 1016 float4
        #pragma unroll
        for (int i = 0; i < 4; i++) {
            int f = tid + i * 256;
            if (f < 1016) {
                int r  = f >> 3;
                int cg = (f & 7) * 4;
                float4 v = *reinterpret_cast<const float4*>(&Rb[(size_t)r * HD_ + dd + cg]);
                RKs[cg + 0][r] = v.x; RKs[cg + 1][r] = v.y;
                RKs[cg + 2][r] = v.z; RKs[cg + 3][r] = v.w;
            }
        }
        __syncthreads();

        #pragma unroll
        for (int d = 0; d < 32; d++) {
            float4 qv = *reinterpret_cast<const float4*>(&Qs[d][tm * 4]);
            float4 kv = *reinterpret_cast<const float4*>(&Ks[d][tn * 4]);
            float qa[4] = {qv.x, qv.y, qv.z, qv.w};
            float ka[4] = {kv.x, kv.y, kv.z, kv.w};
            float rv[7];
            #pragma unroll
            for (int t = 0; t < 7; t++) rv[t] = RKs[d][base - 3 + t];
            #pragma unroll
            for (int i = 0; i < 4; i++)
                #pragma unroll
                for (int j = 0; j < 4; j++) {
                    accC[i][j] = fmaf(qa[i], ka[j], accC[i][j]);
                    accP[i][j] = fmaf(qa[i], rv[3 + j - i], accP[i][j]);
                }
        }
        __syncthreads();
    }

    const float scale = 0.125f;   // 1/sqrt(64)
    float* out = Sc + (size_t)bh * S_ * S_;
    #pragma unroll
    for (int i = 0; i < 4; i++) {
        int q = q0 + tm * 4 + i;
        float4 o;
        o.x = scale * (accC[i][0] + accP[i][0]);
        o.y = scale * (accC[i][1] + accP[i][1]);
        o.z = scale * (accC[i][2] + accP[i][2]);
        o.w = scale * (accC[i][3] + accP[i][3]);
        *reinterpret_cast<float4*>(&out[(size_t)q * S_ + k0 + tn * 4]) = o;
    }
}

// ==================================================================================
// Row softmax over 1024 entries. One block per row, 256 threads (4 elems each).
// ==================================================================================
__global__ __launch_bounds__(256) void softmax_kernel(float* __restrict__ Sc)
{
    __shared__ float redm[8];
    __shared__ float reds[8];
    float* row = Sc + (size_t)blockIdx.x * S_;
    const int t = threadIdx.x;

    float4 v = reinterpret_cast<float4*>(row)[t];
    float m = fmaxf(fmaxf(v.x, v.y), fmaxf(v.z, v.w));
    #pragma unroll
    for (int o = 16; o > 0; o >>= 1) m = fmaxf(m, __shfl_xor_sync(0xffffffffu, m, o));
    if ((t & 31) == 0) redm[t >> 5] = m;
    __syncthreads();
    if (t == 0) {
        float r = redm[0];
        #pragma unroll
        for (int i = 1; i < 8; i++) r = fmaxf(r, redm[i]);
        redm[0] = r;
    }
    __syncthreads();
    m = redm[0];

    v.x = expf(v.x - m); v.y = expf(v.y - m);
    v.z = expf(v.z - m); v.w = expf(v.w - m);
    float s = v.x + v.y + v.z + v.w;
    #pragma unroll
    for (int o = 16; o > 0; o >>= 1) s += __shfl_xor_sync(0xffffffffu, s, o);
    if ((t & 31) == 0) reds[t >> 5] = s;
    __syncthreads();
    if (t == 0) {
        float r = 0.f;
        #pragma unroll
        for (int i = 0; i < 8; i++) r += reds[i];
        reds[0] = r;
    }
    __syncthreads();
    float inv = 1.0f / reds[0];
    v.x *= inv; v.y *= inv; v.z *= inv; v.w *= inv;
    reinterpret_cast<float4*>(row)[t] = v;
}

// ==================================================================================
// ctx[b, q, h*64+d] = sum_k probs[bh, q, k] * V[bh, k, d]
// Block: (q-tile 64) x (bh). 256 threads, 4x4 microtile, k chunks of 64.
// ==================================================================================
__global__ __launch_bounds__(256) void pv_kernel(
    const float* __restrict__ P, const float* __restrict__ V, float* __restrict__ ctx)
{
    __shared__ __align__(16) float Ps[64][68];   // [k][q]
    __shared__ __align__(16) float Vs[64][68];   // [k][d]
    const int bh = blockIdx.y;
    const int q0 = blockIdx.x * 64;
    const int tid = threadIdx.x;
    const int tm  = tid >> 4;   // q group
    const int tn  = tid & 15;   // d group

    const float* Pb = P + (size_t)bh * S_ * S_;
    const float* Vb = V + (size_t)bh * S_ * HD_;

    float acc[4][4];
    #pragma unroll
    for (int i = 0; i < 4; i++)
        #pragma unroll
        for (int j = 0; j < 4; j++) acc[i][j] = 0.f;

    for (int k0 = 0; k0 < S_; k0 += 64) {
        // P tile [64 q][64 k] -> transposed Ps[k][q]; 1024 float4, 4 per thread
        #pragma unroll
        for (int i = 0; i < 4; i++) {
            int f  = tid + i * 256;
            int r  = f >> 4;            // q row
            int cg = (f & 15) * 4;      // k group
            float4 v = *reinterpret_cast<const float4*>(&Pb[(size_t)(q0 + r) * S_ + k0 + cg]);
            Ps[cg + 0][r] = v.x; Ps[cg + 1][r] = v.y;
            Ps[cg + 2][r] = v.z; Ps[cg + 3][r] = v.w;
        }
        // V tile [64 k][64 d] direct layout
        #pragma unroll
        for (int i = 0; i < 4; i++) {
            int f  = tid + i * 256;
            int r  = f >> 4;            // k row
            int cg = (f & 15) * 4;      // d group
            float4 v = *reinterpret_cast<const float4*>(&Vb[(size_t)(k0 + r) * HD_ + cg]);
            *reinterpret_cast<float4*>(&Vs[r][cg]) = v;
        }
        __syncthreads();
        #pragma unroll
        for (int k = 0; k < 64; k++) {
            float4 pv = *reinterpret_cast<const float4*>(&Ps[k][tm * 4]);
            float4 vv = *reinterpret_cast<const float4*>(&Vs[k][tn * 4]);
            float pa[4] = {pv.x, pv.y, pv.z, pv.w};
            float va[4] = {vv.x, vv.y, vv.z, vv.w};
            #pragma unroll
            for (int i = 0; i < 4; i++)
                #pragma unroll
                for (int j = 0; j < 4; j++)
                    acc[i][j] = fmaf(pa[i], va[j], acc[i][j]);
        }
        __syncthreads();
    }

    const int bb = bh >> 4;     // H = 16
    const int hh = bh & 15;
    #pragma unroll
    for (int i = 0; i < 4; i++) {
        int q = q0 + tm * 4 + i;
        float4 o = make_float4(acc[i][0], acc[i][1], acc[i][2], acc[i][3]);
        size_t idx = ((size_t)bb * S_ + q) * E_ + hh * HD_ + tn * 4;
        *reinterpret_cast<float4*>(&ctx[idx]) = o;
    }
}

// ==================================================================================
// Launch
// ==================================================================================
extern "C" void kernel_launch(void* const* d_in, const int* in_sizes, int n_in,
                              void* d_out, int out_size)
{
    const float* x   = (const float*)d_in[0];
    const float* Wq  = (const float*)d_in[1];
    const float* bq  = (const float*)d_in[2];
    const float* Wk  = (const float*)d_in[3];
    const float* bk  = (const float*)d_in[4];
    const float* Wv  = (const float*)d_in[5];
    const float* bv  = (const float*)d_in[6];
    const float* Wo  = (const float*)d_in[7];
    const float* bo  = (const float*)d_in[8];
    const float* Wp  = (const float*)d_in[9];
    const float* rel = (const float*)d_in[10];
    float* out = (float*)d_out;

    float *Qp, *Kp, *Vp, *ctxp, *rkp, *scp;
    cudaGetSymbolAddress((void**)&Qp,   g_Q);
    cudaGetSymbolAddress((void**)&Kp,   g_K);
    cudaGetSymbolAddress((void**)&Vp,   g_V);
    cudaGetSymbolAddress((void**)&ctxp, g_ctx);
    cudaGetSymbolAddress((void**)&rkp,  g_relkey);
    cudaGetSymbolAddress((void**)&scp,  g_scores);

    dim3 gemmGrid(E_ / 128, (B_ * S_) / 128);   // (8, 32)

    gemm_nt_bias<<<gemmGrid, 256>>>(x, Wq, bq, Qp, B_ * S_, E_, E_, 1);
    gemm_nt_bias<<<gemmGrid, 256>>>(x, Wk, bk, Kp, B_ * S_, E_, E_, 1);
    gemm_nt_bias<<<gemmGrid, 256>>>(x, Wv, bv, Vp, B_ * S_, E_, E_, 1);

    relkey_kernel<<<RELN_, 64>>>(rel, Wp, rkp);

    scores_kernel<<<dim3(S_ / 64, S_ / 64, BH_), 256>>>(Qp, Kp, rkp, scp);

    softmax_kernel<<<BH_ * S_, 256>>>(scp);

    pv_kernel<<<dim3(S_ / 64, BH_), 256>>>(scp, Vp, ctxp);

    gemm_nt_bias<<<gemmGrid, 256>>>(ctxp, Wo, bo, out, B_ * S_, E_, E_, 0);
}